// round 3
// baseline (speedup 1.0000x reference)
#include <cuda_runtime.h>
#include <cstdint>

#define BATCH 32
#define SEQ_LEN 4096
#define D_MODEL 256
#define STATE_N 64
#define N_CLASSES 5
#define C_CHUNKS 16
#define T_CHUNK (SEQ_LEN / C_CHUNKS)   /* 256 */
#define NPAIR 16                       /* f32x2 pairs per thread -> 32 states */

// Scratch (no cudaMalloc allowed): chunk-boundary states + per-chunk pool partials
__device__ float g_scratch[BATCH * C_CHUNKS * D_MODEL * STATE_N];  // 33.5 MB
__device__ float g_pool[BATCH * D_MODEL * C_CHUNKS * 2];           // 1 MB

typedef unsigned long long ull;

__device__ __forceinline__ ull pk2(float lo, float hi) {
    ull r; asm("mov.b64 %0, {%1, %2};" : "=l"(r) : "f"(lo), "f"(hi)); return r;
}
__device__ __forceinline__ void upk2(ull v, float &lo, float &hi) {
    asm("mov.b64 {%0, %1}, %2;" : "=f"(lo), "=f"(hi) : "l"(v));
}
__device__ __forceinline__ ull ffma2(ull a, ull b, ull c) {
    ull d; asm("fma.rn.f32x2 %0, %1, %2, %3;" : "=l"(d) : "l"(a), "l"(b), "l"(c)); return d;
}
__device__ __forceinline__ ull fmul2(ull a, ull b) {
    ull d; asm("mul.rn.f32x2 %0, %1, %2;" : "=l"(d) : "l"(a), "l"(b)); return d;
}
__device__ __forceinline__ ull fadd2(ull a, ull b) {
    ull d; asm("add.rn.f32x2 %0, %1, %2;" : "=l"(d) : "l"(a), "l"(b)); return d;
}

// ---------------- Pass 1: per-chunk local final states (zero-seeded) ----------------
__global__ __launch_bounds__(256, 2)
void pass1_chunk_states(const float* __restrict__ x,
                        const float* __restrict__ w_in,
                        const float* __restrict__ b_in,
                        const float* __restrict__ A_diag) {
    __shared__ float shx[T_CHUNK];
    const int c = blockIdx.x, dh = blockIdx.y, b = blockIdx.z;
    const int tid = threadIdx.x;
    const int d = dh * 128 + (tid >> 1);
    const int half = tid & 1;
    shx[tid] = x[b * SEQ_LEN + c * T_CHUNK + tid];

    const float2* A2 = reinterpret_cast<const float2*>(A_diag + d * STATE_N + half * 32);
    ull a2[NPAIR];
    #pragma unroll
    for (int j = 0; j < NPAIR; j++) { float2 v = A2[j]; a2[j] = pk2(v.x, v.y); }
    const float w = w_in[d], bi = b_in[d];
    __syncthreads();

    ull r[NPAIR];
    #pragma unroll
    for (int j = 0; j < NPAIR; j++) r[j] = 0ull;

    #pragma unroll 4
    for (int t = 0; t < T_CHUNK; t++) {
        float u = fmaf(shx[t], w, bi);
        ull u2 = pk2(u, u);
        #pragma unroll
        for (int j = 0; j < NPAIR; j++) r[j] = ffma2(a2[j], r[j], u2);
    }
    float2* outp = reinterpret_cast<float2*>(
        g_scratch + ((size_t)(b * C_CHUNKS + c) * D_MODEL + d) * STATE_N + half * 32);
    #pragma unroll
    for (int j = 0; j < NPAIR; j++) { float2 o; upk2(r[j], o.x, o.y); outp[j] = o; }
}

// ---------------- Pass 2: inter-chunk scan, converts local finals -> chunk seeds ----------------
__global__ void pass2_scan(const float* __restrict__ A_diag) {
    int i = blockIdx.x * blockDim.x + threadIdx.x;  // < B*D*N
    int b = i >> 14;          // D*N = 16384
    int rem = i & 16383;
    int d = rem >> 6;
    int n = rem & 63;
    float a = A_diag[d * STATE_N + n];
    float aL = a;
    #pragma unroll
    for (int k = 0; k < 8; k++) aL *= aL;   // a^256 = a^T_CHUNK
    float r = 0.f;                          // true state at start of chunk 0
    int idx = b * (C_CHUNKS * D_MODEL * STATE_N) + d * STATE_N + n;
    #pragma unroll
    for (int c = 0; c < C_CHUNKS; c++) {
        float f = g_scratch[idx];           // local final of chunk c
        g_scratch[idx] = r;                 // seed for chunk c
        r = fmaf(aL, r, f);                 // true state at start of chunk c+1
        idx += D_MODEL * STATE_N;
    }
}

// ---------------- Pass 3: seeded recurrence + readout + gelu + chunk pooling ----------------
__global__ __launch_bounds__(256, 2)
void pass3_main(const float* __restrict__ x,
                const float* __restrict__ w_in,
                const float* __restrict__ b_in,
                const float* __restrict__ A_diag,
                const float* __restrict__ B_in,
                const float* __restrict__ C_out,
                const float* __restrict__ D_skip) {
    __shared__ float shx[T_CHUNK];
    const int c = blockIdx.x, dh = blockIdx.y, b = blockIdx.z;
    const int tid = threadIdx.x;
    const int d = dh * 128 + (tid >> 1);
    const int half = tid & 1;
    shx[tid] = x[b * SEQ_LEN + c * T_CHUNK + tid];

    const float2* A2 = reinterpret_cast<const float2*>(A_diag + d * STATE_N + half * 32);
    const float2* B2 = reinterpret_cast<const float2*>(B_in  + d * STATE_N + half * 32);
    const float2* C2 = reinterpret_cast<const float2*>(C_out + d * STATE_N + half * 32);
    ull a2[NPAIR], gg[NPAIR];
    #pragma unroll
    for (int j = 0; j < NPAIR; j++) {
        float2 av = A2[j]; float2 bv = B2[j]; float2 cv = C2[j];
        a2[j] = pk2(av.x, av.y);
        gg[j] = pk2(bv.x * cv.x, bv.y * cv.y);   // g_n = C_n * B_n (state rescale trick)
    }
    const float w = w_in[d], bi = b_in[d], dsk = D_skip[d];

    const float2* seedp = reinterpret_cast<const float2*>(
        g_scratch + ((size_t)(b * C_CHUNKS + c) * D_MODEL + d) * STATE_N + half * 32);
    ull r[NPAIR];
    #pragma unroll
    for (int j = 0; j < NPAIR; j++) { float2 sv = seedp[j]; r[j] = pk2(sv.x, sv.y); }
    __syncthreads();

    float psum = 0.f;
    float pmax = -3.402823466e38f;

    #pragma unroll 2
    for (int t = 0; t < T_CHUNK; t++) {
        float u = fmaf(shx[t], w, bi);
        ull u2 = pk2(u, u);
        #pragma unroll
        for (int j = 0; j < NPAIR; j++) r[j] = ffma2(a2[j], r[j], u2);
        ull acc0 = fmul2(gg[0], r[0]);
        ull acc1 = fmul2(gg[1], r[1]);
        ull acc2 = fmul2(gg[2], r[2]);
        ull acc3 = fmul2(gg[3], r[3]);
        #pragma unroll
        for (int j = 4; j < NPAIR; j += 4) {
            acc0 = ffma2(gg[j+0], r[j+0], acc0);
            acc1 = ffma2(gg[j+1], r[j+1], acc1);
            acc2 = ffma2(gg[j+2], r[j+2], acc2);
            acc3 = ffma2(gg[j+3], r[j+3], acc3);
        }
        acc0 = fadd2(acc0, acc1);
        acc2 = fadd2(acc2, acc3);
        acc0 = fadd2(acc0, acc2);
        float lo, hi; upk2(acc0, lo, hi);
        float yp = lo + hi;
        yp += __shfl_xor_sync(0xffffffffu, yp, 1);   // join the two n-halves
        float ypre = fmaf(dsk, u, yp);
        // jax.nn.gelu approximate=True: 0.5*x*(1+tanh(sqrt(2/pi)*(x+0.044715 x^3)))
        float inner = 0.7978845608028654f * ypre * fmaf(0.044715f, ypre * ypre, 1.0f);
        float th; asm("tanh.approx.f32 %0, %1;" : "=f"(th) : "f"(inner));
        float h = 0.5f * ypre * (1.0f + th);
        psum += h;
        pmax = fmaxf(pmax, h);
    }
    if (half == 0) {
        float* pp = g_pool + ((size_t)(b * D_MODEL + d) * C_CHUNKS + c) * 2;
        pp[0] = psum;
        pp[1] = pmax;
    }
}

// ---------------- Pass 4: pool across chunks + head matmul ----------------
__global__ void pass4_head(const float* __restrict__ W_head,
                           const float* __restrict__ b_head,
                           float* __restrict__ out) {
    const int b = blockIdx.x;
    const int d = threadIdx.x;   // 256 threads
    const float* pp = g_pool + ((size_t)(b * D_MODEL + d)) * C_CHUNKS * 2;
    float s = 0.f, m = -3.402823466e38f;
    #pragma unroll
    for (int c = 0; c < C_CHUNKS; c++) { s += pp[2 * c]; m = fmaxf(m, pp[2 * c + 1]); }
    float avg = s * (1.0f / (float)SEQ_LEN);
    float contrib[N_CLASSES];
    #pragma unroll
    for (int k = 0; k < N_CLASSES; k++)
        contrib[k] = avg * W_head[d * N_CLASSES + k]
                   + m   * W_head[(D_MODEL + d) * N_CLASSES + k];
    __shared__ float red[8][N_CLASSES];
    int lane = d & 31, wid = d >> 5;
    #pragma unroll
    for (int k = 0; k < N_CLASSES; k++) {
        float v = contrib[k];
        #pragma unroll
        for (int o = 16; o > 0; o >>= 1) v += __shfl_xor_sync(0xffffffffu, v, o);
        if (lane == 0) red[wid][k] = v;
    }
    __syncthreads();
    if (d == 0) {
        #pragma unroll
        for (int k = 0; k < N_CLASSES; k++) {
            float t = b_head[k];
            #pragma unroll
            for (int wq = 0; wq < 8; wq++) t += red[wq][k];
            out[b * N_CLASSES + k] = t;
        }
    }
}

extern "C" void kernel_launch(void* const* d_in, const int* in_sizes, int n_in,
                              void* d_out, int out_size) {
    const float* x      = (const float*)d_in[0];
    const float* w_in   = (const float*)d_in[1];
    const float* b_in   = (const float*)d_in[2];
    const float* A_diag = (const float*)d_in[3];
    const float* B_in   = (const float*)d_in[4];
    const float* C_out  = (const float*)d_in[5];
    const float* D_skip = (const float*)d_in[6];
    const float* W_head = (const float*)d_in[7];
    const float* b_head = (const float*)d_in[8];
    float* out = (float*)d_out;

    dim3 g13(C_CHUNKS, 2, BATCH);
    pass1_chunk_states<<<g13, 256>>>(x, w_in, b_in, A_diag);
    pass2_scan<<<(BATCH * D_MODEL * STATE_N) / 256, 256>>>(A_diag);
    pass3_main<<<g13, 256>>>(x, w_in, b_in, A_diag, B_in, C_out, D_skip);
    pass4_head<<<BATCH, 256>>>(W_head, b_head, out);
}

// round 5
// speedup vs baseline: 1.5952x; 1.5952x over previous
#include <cuda_runtime.h>
#include <cuda_bf16.h>
#include <cstdint>

#define BATCH 32
#define T_TOTAL 4096
#define DM 256
#define SN 64
#define NCLS 5
#define L 64
#define CCH 64                /* chunks per batch */
#define MT 16                 /* (BATCH*CCH)/128 row tiles */

// ---- device scratch (no cudaMalloc allowed) ----
__device__ float g_P[DM * SN * L];     // [d][n][tau] = a^(L-1-tau)
__device__ float g_Q[DM * L * SN];     // [d][i][n]   = g*a^(i+1)
__device__ float g_M[DM * L * L];      // [d][i][tau] = w*K[i-tau] (+dsk*w on diag)
__device__ float g_beta[DM * L];       // [d][i] = b*kappa[i] + dsk*b
__device__ float g_zeta[DM * SN];
__device__ float g_aL[DM * SN];
__device__ float g_pool[BATCH * DM * 2];

// ---- smem layout (bytes) ----
#define PITCH 144              /* bf16 row pitch: 72 elems, ldmatrix conflict-free */
#define OFF_BETA 0             /* 64 f32 */
#define OFF_WP   256           /* 16 f32 */
#define OFF_XH   512
#define OFF_XL   (OFF_XH + 128 * PITCH)   /* 18944 */
#define OFF_SH   (OFF_XL + 128 * PITCH)   /* 37376 */
#define OFF_SL   (OFF_SH + 128 * PITCH)   /* 55808 */
#define OFF_U    (OFF_SL + 128 * PITCH)   /* 74240 union: P | F | M+Q */
#define OFF_PH   OFF_U
#define OFF_PL   (OFF_U + 64 * PITCH)
#define OFF_F    OFF_U                     /* 128 x 66 f32 = 33792 */
#define FPITCH   66
#define OFF_MH   OFF_U
#define OFF_ML   (OFF_U + 64 * PITCH)
#define OFF_QH   (OFF_U + 2 * 64 * PITCH)
#define OFF_QL   (OFF_U + 3 * 64 * PITCH)
#define SMEM_BYTES (OFF_U + 4 * 64 * PITCH)   /* 111104 */

__device__ __forceinline__ uint32_t smem_u32(const void* p) {
    uint32_t a;
    asm("{ .reg .u64 t; cvta.to.shared.u64 t, %1; cvt.u32.u64 %0, t; }" : "=r"(a) : "l"(p));
    return a;
}
__device__ __forceinline__ void ldsm4(uint32_t addr, uint32_t r[4]) {
    asm volatile("ldmatrix.sync.aligned.m8n8.x4.shared.b16 {%0,%1,%2,%3}, [%4];"
                 : "=r"(r[0]), "=r"(r[1]), "=r"(r[2]), "=r"(r[3]) : "r"(addr));
}
__device__ __forceinline__ void mma16816(float c[4], const uint32_t a[4], const uint32_t b0, const uint32_t b1) {
    asm volatile("mma.sync.aligned.m16n8k16.row.col.f32.bf16.bf16.f32 "
                 "{%0,%1,%2,%3}, {%4,%5,%6,%7}, {%8,%9}, {%0,%1,%2,%3};"
                 : "+f"(c[0]), "+f"(c[1]), "+f"(c[2]), "+f"(c[3])
                 : "r"(a[0]), "r"(a[1]), "r"(a[2]), "r"(a[3]), "r"(b0), "r"(b1));
}
__device__ __forceinline__ void cvt_hl(float v, __nv_bfloat16& h, __nv_bfloat16& l) {
    h = __float2bfloat16(v);
    l = __float2bfloat16(v - __bfloat162float(h));
}
__device__ __forceinline__ void sts_hl4(char* smem, int hoff, int loff, int row, int col,
                                        float v0, float v1, float v2, float v3) {
    __nv_bfloat16 h0, l0, h1, l1, h2, l2, h3, l3;
    cvt_hl(v0, h0, l0); cvt_hl(v1, h1, l1); cvt_hl(v2, h2, l2); cvt_hl(v3, h3, l3);
    int off = row * PITCH + col * 2;
    __nv_bfloat162 a, b;
    a.x = h0; a.y = h1; b.x = h2; b.y = h3;
    *reinterpret_cast<__nv_bfloat162*>(smem + hoff + off) = a;
    *reinterpret_cast<__nv_bfloat162*>(smem + hoff + off + 4) = b;
    a.x = l0; a.y = l1; b.x = l2; b.y = l3;
    *reinterpret_cast<__nv_bfloat162*>(smem + loff + off) = a;
    *reinterpret_cast<__nv_bfloat162*>(smem + loff + off + 4) = b;
}

// 3-product split matmul-accumulate: C[16 rows x 64 cols] += (Ah+Al)*(Bh+Bl) approx
__device__ __forceinline__ void mm3(float C[8][4], uint32_t aH, uint32_t aL,
                                    uint32_t bH, uint32_t bL, int lane, int row0) {
    const uint32_t aoff = (uint32_t)(row0 + (lane & 15)) * PITCH + ((lane >> 4) & 1) * 16;
    const uint32_t brow = (uint32_t)(((lane >> 3) & 2) * 4 + (lane & 7));
    const uint32_t bkoff = ((lane >> 3) & 1) * 16;
    #pragma unroll
    for (int kc = 0; kc < 4; kc++) {
        uint32_t ah[4], al[4];
        ldsm4(aH + aoff + kc * 32, ah);
        ldsm4(aL + aoff + kc * 32, al);
        #pragma unroll
        for (int j = 0; j < 4; j++) {
            uint32_t boff = (j * 16 + brow) * PITCH + bkoff + kc * 32;
            uint32_t bh[4], bl[4];
            ldsm4(bH + boff, bh);
            ldsm4(bL + boff, bl);
            mma16816(C[2 * j],     ah, bh[0], bh[1]);
            mma16816(C[2 * j],     ah, bl[0], bl[1]);
            mma16816(C[2 * j],     al, bh[0], bh[1]);
            mma16816(C[2 * j + 1], ah, bh[2], bh[3]);
            mma16816(C[2 * j + 1], ah, bl[2], bl[3]);
            mma16816(C[2 * j + 1], al, bh[2], bh[3]);
        }
    }
}

// ---------------- precompute per-d operator tiles ----------------
__global__ void precompute(const float* __restrict__ w_in, const float* __restrict__ b_in,
                           const float* __restrict__ A_diag, const float* __restrict__ B_in,
                           const float* __restrict__ C_out, const float* __restrict__ D_skip) {
    const int d = blockIdx.x;
    const int n = threadIdx.x;          // 64
    __shared__ float gm[L * SN];
    __shared__ float K[L], kap[L];
    float a = A_diag[d * SN + n];
    float g = B_in[d * SN + n] * C_out[d * SN + n];

    float pw = 1.f, zeta = 0.f;
    for (int t = L - 1; t >= 0; t--) { g_P[(d * SN + n) * L + t] = pw; zeta += pw; pw *= a; }
    g_zeta[d * SN + n] = zeta;
    g_aL[d * SN + n] = pw;

    float q = g * a;
    for (int i = 0; i < L; i++) { g_Q[(d * L + i) * SN + n] = q; q *= a; }

    float v = g;
    for (int dd = 0; dd < L; dd++) { gm[dd * SN + n] = v; v *= a; }
    __syncthreads();
    { float s = 0.f; for (int k = 0; k < SN; k++) s += gm[n * SN + k]; K[n] = s; }
    __syncthreads();
    if (n == 0) { float acc = 0.f; for (int i = 0; i < L; i++) { acc += K[i]; kap[i] = acc; } }
    __syncthreads();
    float w = w_in[d], bb = b_in[d], dsk = D_skip[d];
    { int i = n;
      for (int t = 0; t < L; t++) {
          float val = (t <= i) ? w * K[i - t] : 0.f;
          if (t == i) val += dsk * w;               // fold D_skip * w * x[i]
          g_M[(d * L + i) * L + t] = val;
      }
      g_beta[d * L + i] = bb * kap[i] + dsk * bb; } // fold D_skip * b
}

// ---------------- fused SSM: one CTA per (row-tile m, channel d) ----------------
__global__ __launch_bounds__(256, 2)
void ssm_mma(const float* __restrict__ x, const float* __restrict__ w_in,
             const float* __restrict__ b_in) {
    extern __shared__ char smem[];
    const uint32_t sb = smem_u32(smem);
    const int tid = threadIdx.x, wid = tid >> 5, lane = tid & 31;
    const int m = blockIdx.x, d = blockIdx.y;
    const float w = w_in[d], bi = b_in[d];

    // phase 0: stage X hi/lo, P hi/lo, beta
    if (tid < 64) reinterpret_cast<float*>(smem + OFF_BETA)[tid] = g_beta[d * L + tid];
    {
        int r = tid >> 1, t0 = (tid & 1) * 32;
        int bcg = m * 128 + r, b = bcg >> 6, c = bcg & 63;
        const float4* xp = reinterpret_cast<const float4*>(x + b * T_TOTAL + c * L + t0);
        #pragma unroll
        for (int k = 0; k < 8; k++) {
            float4 v = xp[k];
            sts_hl4(smem, OFF_XH, OFF_XL, r, t0 + 4 * k, v.x, v.y, v.z, v.w);
        }
    }
    {
        int n = tid >> 2, t0 = (tid & 3) * 16;
        const float4* pp = reinterpret_cast<const float4*>(g_P + (d * SN + n) * L + t0);
        #pragma unroll
        for (int k = 0; k < 4; k++) {
            float4 v = pp[k];
            sts_hl4(smem, OFF_PH, OFF_PL, n, t0 + 4 * k, v.x, v.y, v.z, v.w);
        }
    }
    __syncthreads();

    // phase 1: F = X . P^T  (each warp: 16 rows)
    {
        float C1[8][4];
        #pragma unroll
        for (int i = 0; i < 8; i++)
            #pragma unroll
            for (int k = 0; k < 4; k++) C1[i][k] = 0.f;
        mm3(C1, sb + OFF_XH, sb + OFF_XL, sb + OFF_PH, sb + OFF_PL, lane, wid * 16);
        __syncthreads();   // P region dead before F overwrite
        float* F = reinterpret_cast<float*>(smem + OFF_F);
        int rg = wid * 16 + (lane >> 2);
        int cb = (lane & 3) * 2;
        #pragma unroll
        for (int nt = 0; nt < 8; nt++) {
            float2 v0, v1;
            v0.x = C1[nt][0]; v0.y = C1[nt][1];
            v1.x = C1[nt][2]; v1.y = C1[nt][3];
            *reinterpret_cast<float2*>(F + rg * FPITCH + nt * 8 + cb) = v0;
            *reinterpret_cast<float2*>(F + (rg + 8) * FPITCH + nt * 8 + cb) = v1;
        }
    }
    __syncthreads();

    // phase 2: inter-chunk scan -> seeds S hi/lo
    if (tid < 128) {
        int bl = tid >> 6, n = tid & 63;
        float aLv = g_aL[d * SN + n];
        float bz = bi * g_zeta[d * SN + n];
        const float* F = reinterpret_cast<const float*>(smem + OFF_F);
        float r = 0.f;
        #pragma unroll 4
        for (int c = 0; c < CCH; c++) {
            int row = bl * 64 + c;
            __nv_bfloat16 hh, ll;
            cvt_hl(r, hh, ll);
            *reinterpret_cast<__nv_bfloat16*>(smem + OFF_SH + row * PITCH + n * 2) = hh;
            *reinterpret_cast<__nv_bfloat16*>(smem + OFF_SL + row * PITCH + n * 2) = ll;
            float Fv = F[row * FPITCH + n];
            r = fmaf(aLv, r, fmaf(w, Fv, bz));
        }
    }
    __syncthreads();

    // phase 3: stage M', Q hi/lo (overwrites F region)
    {
        int i = tid >> 2, q = tid & 3, t0 = q * 16;
        const float4* mp = reinterpret_cast<const float4*>(g_M + (d * L + i) * L + t0);
        const float4* qp = reinterpret_cast<const float4*>(g_Q + (d * L + i) * SN + t0);
        #pragma unroll
        for (int k = 0; k < 4; k++) {
            float4 v = mp[k];
            sts_hl4(smem, OFF_MH, OFF_ML, i, t0 + 4 * k, v.x, v.y, v.z, v.w);
            float4 u = qp[k];
            sts_hl4(smem, OFF_QH, OFF_QL, i, t0 + 4 * k, u.x, u.y, u.z, u.w);
        }
    }
    __syncthreads();

    // phase 4: y = X.M'^T + S.Q^T ; epilogue gelu + pool
    {
        float C2[8][4];
        #pragma unroll
        for (int i = 0; i < 8; i++)
            #pragma unroll
            for (int k = 0; k < 4; k++) C2[i][k] = 0.f;
        mm3(C2, sb + OFF_XH, sb + OFF_XL, sb + OFF_MH, sb + OFF_ML, lane, wid * 16);
        mm3(C2, sb + OFF_SH, sb + OFF_SL, sb + OFF_QH, sb + OFF_QL, lane, wid * 16);

        const float* beta = reinterpret_cast<const float*>(smem + OFF_BETA);
        float ps = 0.f, pm = -3.402823466e38f;
        #pragma unroll
        for (int nt = 0; nt < 8; nt++) {
            float2 b2 = *reinterpret_cast<const float2*>(beta + nt * 8 + (lane & 3) * 2);
            #pragma unroll
            for (int k = 0; k < 4; k++) {
                float ypre = C2[nt][k] + ((k & 1) ? b2.y : b2.x);
                float inner = 0.7978845608028654f * ypre * fmaf(0.044715f, ypre * ypre, 1.0f);
                float th; asm("tanh.approx.f32 %0, %1;" : "=f"(th) : "f"(inner));
                float h = 0.5f * ypre * (1.0f + th);
                ps += h;
                pm = fmaxf(pm, h);
            }
        }
        #pragma unroll
        for (int o = 16; o > 0; o >>= 1) {
            ps += __shfl_xor_sync(0xffffffffu, ps, o);
            pm = fmaxf(pm, __shfl_xor_sync(0xffffffffu, pm, o));
        }
        float* wp = reinterpret_cast<float*>(smem + OFF_WP);
        if (lane == 0) { wp[wid * 2] = ps; wp[wid * 2 + 1] = pm; }
    }
    __syncthreads();
    if (tid < 2) {
        const float* wp = reinterpret_cast<const float*>(smem + OFF_WP);
        int w0 = tid * 4;   // warps 0-3 -> b_local 0, warps 4-7 -> b_local 1
        float s = wp[(w0 + 0) * 2] + wp[(w0 + 1) * 2] + wp[(w0 + 2) * 2] + wp[(w0 + 3) * 2];
        float mx = fmaxf(fmaxf(wp[(w0 + 0) * 2 + 1], wp[(w0 + 1) * 2 + 1]),
                         fmaxf(wp[(w0 + 2) * 2 + 1], wp[(w0 + 3) * 2 + 1]));
        int b = m * 2 + tid;
        g_pool[(b * DM + d) * 2] = s;
        g_pool[(b * DM + d) * 2 + 1] = mx;
    }
}

// ---------------- head ----------------
__global__ void head_kernel(const float* __restrict__ W_head, const float* __restrict__ b_head,
                            float* __restrict__ out) {
    const int b = blockIdx.x;
    const int d = threadIdx.x;   // 256
    float avg = g_pool[(b * DM + d) * 2] * (1.0f / (float)T_TOTAL);
    float mx = g_pool[(b * DM + d) * 2 + 1];
    float contrib[NCLS];
    #pragma unroll
    for (int k = 0; k < NCLS; k++)
        contrib[k] = avg * W_head[d * NCLS + k] + mx * W_head[(DM + d) * NCLS + k];
    __shared__ float red[8][NCLS];
    int lane = d & 31, wid = d >> 5;
    #pragma unroll
    for (int k = 0; k < NCLS; k++) {
        float v = contrib[k];
        #pragma unroll
        for (int o = 16; o > 0; o >>= 1) v += __shfl_xor_sync(0xffffffffu, v, o);
        if (lane == 0) red[wid][k] = v;
    }
    __syncthreads();
    if (d == 0) {
        #pragma unroll
        for (int k = 0; k < NCLS; k++) {
            float t = b_head[k];
            #pragma unroll
            for (int wq = 0; wq < 8; wq++) t += red[wq][k];
            out[b * NCLS + k] = t;
        }
    }
}

extern "C" void kernel_launch(void* const* d_in, const int* in_sizes, int n_in,
                              void* d_out, int out_size) {
    const float* x      = (const float*)d_in[0];
    const float* w_in   = (const float*)d_in[1];
    const float* b_in   = (const float*)d_in[2];
    const float* A_diag = (const float*)d_in[3];
    const float* B_in   = (const float*)d_in[4];
    const float* C_out  = (const float*)d_in[5];
    const float* D_skip = (const float*)d_in[6];
    const float* W_head = (const float*)d_in[7];
    const float* b_head = (const float*)d_in[8];
    float* out = (float*)d_out;

    cudaFuncSetAttribute(ssm_mma, cudaFuncAttributeMaxDynamicSharedMemorySize, SMEM_BYTES);
    precompute<<<DM, 64>>>(w_in, b_in, A_diag, B_in, C_out, D_skip);
    ssm_mma<<<dim3(MT, DM), 256, SMEM_BYTES>>>(x, w_in, b_in);
    head_kernel<<<BATCH, 256>>>(W_head, b_head, out);
}

// round 6
// speedup vs baseline: 2.1474x; 1.3462x over previous
#include <cuda_runtime.h>
#include <cuda_bf16.h>
#include <cuda_fp16.h>
#include <cstdint>

#define BATCH 32
#define T_TOTAL 4096
#define DM 256
#define SN 64
#define NCLS 5
#define L 64
#define CCH 64
#define MT 16

// ---- gmem precomputed operands (pre-swizzled bf16/fp16 hi+lo) ----
__device__ __nv_bfloat16 g_xh[BATCH * T_TOTAL], g_xl[BATCH * T_TOTAL];
__device__ __nv_bfloat16 g_Ph[DM * 4096], g_Pl[DM * 4096];
__device__ __nv_bfloat16 g_Mh[DM * 4096], g_Ml[DM * 4096];
__device__ __half        g_Qh[DM * 4096], g_Ql[DM * 4096];
__device__ float g_beta[DM * L], g_zeta[DM * SN], g_aL[DM * SN];
__device__ float g_pool[BATCH * DM * 2];

// ---- smem layout (bytes) ----
#define OFF_BETA 0
#define OFF_WP   256
#define OFF_XH   512
#define OFF_XL   16896
#define OFF_SH   33280            /* fp16 seeds, 128 rows x 128B */
#define OFF_U    49664            /* P(hi/lo) then M(hi/lo), 16KB */
#define OFF_QH   66048
#define OFF_QL   74240
#define OFF_F    82432            /* fp16, 128 rows x 66 elems (132B) */
#define SMEM_BYTES 99328

__device__ __forceinline__ uint32_t smem_u32(const void* p) {
    uint32_t a;
    asm("{ .reg .u64 t; cvta.to.shared.u64 t, %1; cvt.u32.u64 %0, t; }" : "=r"(a) : "l"(p));
    return a;
}
#define CP16(dst, src) asm volatile("cp.async.cg.shared.global [%0], [%1], 16;" :: "r"(dst), "l"(src))
#define CP_COMMIT()    asm volatile("cp.async.commit_group;" ::: "memory")
#define CP_WAIT0()     asm volatile("cp.async.wait_group 0;" ::: "memory")

__device__ __forceinline__ void ldsm4(uint32_t addr, uint32_t r[4]) {
    asm volatile("ldmatrix.sync.aligned.m8n8.x4.shared.b16 {%0,%1,%2,%3}, [%4];"
                 : "=r"(r[0]), "=r"(r[1]), "=r"(r[2]), "=r"(r[3]) : "r"(addr));
}
__device__ __forceinline__ void mma_bf16(float c[4], const uint32_t a[4], uint32_t b0, uint32_t b1) {
    asm volatile("mma.sync.aligned.m16n8k16.row.col.f32.bf16.bf16.f32 "
                 "{%0,%1,%2,%3}, {%4,%5,%6,%7}, {%8,%9}, {%0,%1,%2,%3};"
                 : "+f"(c[0]), "+f"(c[1]), "+f"(c[2]), "+f"(c[3])
                 : "r"(a[0]), "r"(a[1]), "r"(a[2]), "r"(a[3]), "r"(b0), "r"(b1));
}
__device__ __forceinline__ void mma_f16v(float c[4], const uint32_t a[4], uint32_t b0, uint32_t b1) {
    asm volatile("mma.sync.aligned.m16n8k16.row.col.f32.f16.f16.f32 "
                 "{%0,%1,%2,%3}, {%4,%5,%6,%7}, {%8,%9}, {%0,%1,%2,%3};"
                 : "+f"(c[0]), "+f"(c[1]), "+f"(c[2]), "+f"(c[3])
                 : "r"(a[0]), "r"(a[1]), "r"(a[2]), "r"(a[3]), "r"(b0), "r"(b1));
}
__device__ __forceinline__ void cvt_hl(float v, __nv_bfloat16& h, __nv_bfloat16& l) {
    h = __float2bfloat16(v);
    l = __float2bfloat16(v - __bfloat162float(h));
}
// swizzled elem index within a 128B-row tile (row-major, bf16/fp16 elems)
__device__ __forceinline__ int swzi(int row, int col) {
    return ((row * 128 + col * 2) ^ ((row & 7) << 4)) >> 1;
}

// 3-product bf16 split: C[16x64] += (Ah+Al)(Bh+Bl)
__device__ __forceinline__ void mm3(float C[8][4], uint32_t aH, uint32_t aL,
                                    uint32_t bH, uint32_t bL, int lane, int row0) {
    const int arow = row0 + (lane & 15);
    const uint32_t abase = (uint32_t)arow * 128;
    const uint32_t axor = (uint32_t)(arow & 7) << 4;
    const uint32_t ak16 = ((lane >> 4) & 1) * 16;
    const int brow = ((lane >> 3) & 2) * 4 + (lane & 7);
    const uint32_t bxor = (uint32_t)(brow & 7) << 4;
    const uint32_t bk16 = ((lane >> 3) & 1) * 16;
    #pragma unroll
    for (int kc = 0; kc < 4; kc++) {
        uint32_t acol = (ak16 + kc * 32) ^ axor;
        uint32_t ah[4], al[4];
        ldsm4(aH + abase + acol, ah);
        ldsm4(aL + abase + acol, al);
        #pragma unroll
        for (int j = 0; j < 4; j++) {
            uint32_t boff = (uint32_t)(j * 16 + brow) * 128 + ((bk16 + kc * 32) ^ bxor);
            uint32_t bh[4], bl[4];
            ldsm4(bH + boff, bh);
            ldsm4(bL + boff, bl);
            mma_bf16(C[2 * j],     ah, bh[0], bh[1]);
            mma_bf16(C[2 * j],     ah, bl[0], bl[1]);
            mma_bf16(C[2 * j],     al, bh[0], bh[1]);
            mma_bf16(C[2 * j + 1], ah, bh[2], bh[3]);
            mma_bf16(C[2 * j + 1], ah, bl[2], bl[3]);
            mma_bf16(C[2 * j + 1], al, bh[2], bh[3]);
        }
    }
}
// 2-product fp16: C += S(fp16) * (Qh+Ql)
__device__ __forceinline__ void mm2h(float C[8][4], uint32_t aS,
                                     uint32_t bH, uint32_t bL, int lane, int row0) {
    const int arow = row0 + (lane & 15);
    const uint32_t abase = (uint32_t)arow * 128;
    const uint32_t axor = (uint32_t)(arow & 7) << 4;
    const uint32_t ak16 = ((lane >> 4) & 1) * 16;
    const int brow = ((lane >> 3) & 2) * 4 + (lane & 7);
    const uint32_t bxor = (uint32_t)(brow & 7) << 4;
    const uint32_t bk16 = ((lane >> 3) & 1) * 16;
    #pragma unroll
    for (int kc = 0; kc < 4; kc++) {
        uint32_t acol = (ak16 + kc * 32) ^ axor;
        uint32_t as[4];
        ldsm4(aS + abase + acol, as);
        #pragma unroll
        for (int j = 0; j < 4; j++) {
            uint32_t boff = (uint32_t)(j * 16 + brow) * 128 + ((bk16 + kc * 32) ^ bxor);
            uint32_t bh[4], bl[4];
            ldsm4(bH + boff, bh);
            ldsm4(bL + boff, bl);
            mma_f16v(C[2 * j],     as, bh[0], bh[1]);
            mma_f16v(C[2 * j],     as, bl[0], bl[1]);
            mma_f16v(C[2 * j + 1], as, bh[2], bh[3]);
            mma_f16v(C[2 * j + 1], as, bl[2], bl[3]);
        }
    }
}

// ---------------- x -> bf16 hi/lo, pre-swizzled ----------------
__global__ void xsplit(const float* __restrict__ x) {
    int e = (blockIdx.x * 256 + threadIdx.x) * 4;
    float4 v = *reinterpret_cast<const float4*>(x + e);
    int b = e >> 12, t = e & 4095;
    int rg = b * 64 + (t >> 6), col = t & 63;
    int boff = rg * 128 + ((col * 2) ^ ((rg & 7) << 4));
    float vv[4] = {v.x, v.y, v.z, v.w};
    __nv_bfloat16 h[4], l[4];
    #pragma unroll
    for (int k = 0; k < 4; k++) cvt_hl(vv[k], h[k], l[k]);
    char* ph = (char*)g_xh + boff;
    char* pl = (char*)g_xl + boff;
    __nv_bfloat162 p0, p1;
    p0.x = h[0]; p0.y = h[1]; p1.x = h[2]; p1.y = h[3];
    *(__nv_bfloat162*)ph = p0; *(__nv_bfloat162*)(ph + 4) = p1;
    p0.x = l[0]; p0.y = l[1]; p1.x = l[2]; p1.y = l[3];
    *(__nv_bfloat162*)pl = p0; *(__nv_bfloat162*)(pl + 4) = p1;
}

// ---------------- per-d operator tiles (256 threads/block) ----------------
__global__ void precompute(const float* __restrict__ w_in, const float* __restrict__ b_in,
                           const float* __restrict__ A_diag, const float* __restrict__ B_in,
                           const float* __restrict__ C_out, const float* __restrict__ D_skip) {
    const int d = blockIdx.x;
    const int tid = threadIdx.x;
    const int n = tid & 63, q = tid >> 6;
    __shared__ float gmat[64][65];
    __shared__ float Kp[64][4];
    __shared__ float Ksm[64];
    __shared__ float zp[4][64];

    float a = A_diag[d * 64 + n];
    float g = B_in[d * 64 + n] * C_out[d * 64 + n];
    float a2 = a * a, a4 = a2 * a2, a8 = a4 * a4, a16 = a8 * a8;
    float a32 = a16 * a16, a48 = a32 * a16, a64v = a32 * a32;
    float s = (q == 0) ? 1.f : ((q == 1) ? a16 : ((q == 2) ? a32 : a48));

    {   // P[n][tau] = a^(63-tau); zeta partial
        float p = s, zs = 0.f;
        #pragma unroll
        for (int j = 0; j < 16; j++) {
            int e = q * 16 + j, tau = 63 - e;
            __nv_bfloat16 h, l; cvt_hl(p, h, l);
            int si = d * 4096 + swzi(n, tau);
            g_Ph[si] = h; g_Pl[si] = l;
            zs += p; p *= a;
        }
        zp[q][n] = zs;
    }
    {   // Q[i][n] = g*a^(i+1), fp16 hi/lo
        float t = g * s * a;
        #pragma unroll
        for (int j = 0; j < 16; j++) {
            int i = q * 16 + j;
            __half h = __float2half_rn(t);
            __half l = __float2half_rn(t - __half2float(h));
            int si = d * 4096 + swzi(i, n);
            g_Qh[si] = h; g_Ql[si] = l;
            t *= a;
        }
    }
    {   // gmat[delta][n] = g*a^delta
        float u = g * s;
        #pragma unroll
        for (int j = 0; j < 16; j++) { gmat[q * 16 + j][n] = u; u *= a; }
    }
    __syncthreads();
    if (q == 0) {
        g_zeta[d * 64 + n] = zp[0][n] + zp[1][n] + zp[2][n] + zp[3][n];
        g_aL[d * 64 + n] = a64v;
    }
    {   // K[delta] partial over n
        float ss = 0.f;
        #pragma unroll
        for (int j = 0; j < 16; j++) ss += gmat[n][q * 16 + j];
        Kp[n][q] = ss;
    }
    __syncthreads();
    if (tid < 64) Ksm[tid] = Kp[tid][0] + Kp[tid][1] + Kp[tid][2] + Kp[tid][3];
    __syncthreads();
    float w = w_in[d], bb = b_in[d], dsk = D_skip[d];
    if (tid < 64) {
        float kap = 0.f;
        for (int dd = 0; dd <= tid; dd++) kap += Ksm[dd];
        g_beta[d * 64 + tid] = bb * kap + dsk * bb;
    }
    {   // M[i][tau] = w*K[i-tau] (tau<=i) + dsk*w on diag
        int i = n;
        #pragma unroll
        for (int j = 0; j < 16; j++) {
            int tau = q * 16 + j;
            float val = (tau <= i) ? w * Ksm[i - tau] : 0.f;
            if (tau == i) val += dsk * w;
            __nv_bfloat16 h, l; cvt_hl(val, h, l);
            int si = d * 4096 + swzi(i, tau);
            g_Mh[si] = h; g_Ml[si] = l;
        }
    }
}

// ---------------- fused SSM: one CTA per (row-tile m, channel d) ----------------
__global__ __launch_bounds__(256, 2)
void ssm_mma(const float* __restrict__ w_in, const float* __restrict__ b_in) {
    extern __shared__ char smem[];
    const uint32_t sb = smem_u32(smem);
    const int tid = threadIdx.x, wid = tid >> 5, lane = tid & 31;
    const int m = blockIdx.x, d = blockIdx.y;

    if (tid < 64) reinterpret_cast<float*>(smem + OFF_BETA)[tid] = g_beta[d * 64 + tid];

    {   // cp.async staging: X (hi+lo), P (hi+lo), Q (hi+lo)
        const char* xh = (const char*)g_xh + (size_t)m * 16384;
        const char* xl = (const char*)g_xl + (size_t)m * 16384;
        #pragma unroll
        for (int k = 0; k < 4; k++) {
            int i = (tid + k * 256) * 16;
            CP16(sb + OFF_XH + i, xh + i);
            CP16(sb + OFF_XL + i, xl + i);
        }
        const char* ph = (const char*)g_Ph + d * 8192;
        const char* pl = (const char*)g_Pl + d * 8192;
        const char* qh = (const char*)g_Qh + d * 8192;
        const char* ql = (const char*)g_Ql + d * 8192;
        #pragma unroll
        for (int k = 0; k < 2; k++) {
            int i = (tid + k * 256) * 16;
            CP16(sb + OFF_U + i, ph + i);
            CP16(sb + OFF_U + 8192 + i, pl + i);
            CP16(sb + OFF_QH + i, qh + i);
            CP16(sb + OFF_QL + i, ql + i);
        }
    }
    CP_COMMIT(); CP_WAIT0();
    __syncthreads();

    // MMA1: F = X . P^T (3-product bf16)
    float C1[8][4];
    #pragma unroll
    for (int i = 0; i < 8; i++)
        #pragma unroll
        for (int k = 0; k < 4; k++) C1[i][k] = 0.f;
    mm3(C1, sb + OFF_XH, sb + OFF_XL, sb + OFF_U, sb + OFF_U + 8192, lane, wid * 16);

    {   // store F as fp16 (pitch 66)
        __half* F = reinterpret_cast<__half*>(smem + OFF_F);
        int rg = wid * 16 + (lane >> 2), cb = (lane & 3) * 2;
        #pragma unroll
        for (int nt = 0; nt < 8; nt++) {
            *reinterpret_cast<__half2*>(F + rg * 66 + nt * 8 + cb) =
                __floats2half2_rn(C1[nt][0], C1[nt][1]);
            *reinterpret_cast<__half2*>(F + (rg + 8) * 66 + nt * 8 + cb) =
                __floats2half2_rn(C1[nt][2], C1[nt][3]);
        }
    }
    __syncthreads();

    // warps 0-3: inter-chunk scan -> fp16 seeds | warps 4-7: copy M over dead P
    if (wid < 4) {
        int bl = tid >> 6, n = tid & 63;
        float aLv = g_aL[d * 64 + n];
        float w = w_in[d];
        float bz = b_in[d] * g_zeta[d * 64 + n];
        const __half* F = reinterpret_cast<const __half*>(smem + OFF_F);
        float r = 0.f;
        #pragma unroll 8
        for (int c = 0; c < 64; c++) {
            int row = bl * 64 + c;
            *reinterpret_cast<__half*>(smem + OFF_SH + row * 128 + ((n * 2) ^ ((c & 7) << 4))) =
                __float2half_rn(r);
            r = fmaf(aLv, r, fmaf(w, __half2float(F[row * 66 + n]), bz));
        }
    } else {
        const char* mh = (const char*)g_Mh + d * 8192;
        const char* ml = (const char*)g_Ml + d * 8192;
        int t2 = tid - 128;
        #pragma unroll
        for (int k = 0; k < 4; k++) {
            int i = (t2 + k * 128) * 16;
            CP16(sb + OFF_U + i, mh + i);
            CP16(sb + OFF_U + 8192 + i, ml + i);
        }
        CP_COMMIT(); CP_WAIT0();
    }
    __syncthreads();

    // MMA2: y = X.M'^T (bf16 3-prod) + S.Q^T (fp16 2-prod); epilogue gelu+pool
    float C2[8][4];
    #pragma unroll
    for (int i = 0; i < 8; i++)
        #pragma unroll
        for (int k = 0; k < 4; k++) C2[i][k] = 0.f;
    mm3(C2, sb + OFF_XH, sb + OFF_XL, sb + OFF_U, sb + OFF_U + 8192, lane, wid * 16);
    mm2h(C2, sb + OFF_SH, sb + OFF_QH, sb + OFF_QL, lane, wid * 16);

    {
        const float* beta = reinterpret_cast<const float*>(smem + OFF_BETA);
        float ps = 0.f, pm = -3.402823466e38f;
        #pragma unroll
        for (int nt = 0; nt < 8; nt++) {
            float2 b2 = *reinterpret_cast<const float2*>(beta + nt * 8 + (lane & 3) * 2);
            #pragma unroll
            for (int k = 0; k < 4; k++) {
                float ypre = C2[nt][k] + ((k & 1) ? b2.y : b2.x);
                float inner = 0.7978845608028654f * ypre * fmaf(0.044715f, ypre * ypre, 1.0f);
                float th; asm("tanh.approx.f32 %0, %1;" : "=f"(th) : "f"(inner));
                float h = 0.5f * ypre * (1.0f + th);
                ps += h;
                pm = fmaxf(pm, h);
            }
        }
        #pragma unroll
        for (int o = 16; o > 0; o >>= 1) {
            ps += __shfl_xor_sync(0xffffffffu, ps, o);
            pm = fmaxf(pm, __shfl_xor_sync(0xffffffffu, pm, o));
        }
        float* wp = reinterpret_cast<float*>(smem + OFF_WP);
        if (lane == 0) { wp[wid * 2] = ps; wp[wid * 2 + 1] = pm; }
    }
    __syncthreads();
    if (tid < 2) {
        const float* wp = reinterpret_cast<const float*>(smem + OFF_WP);
        int w0 = tid * 4;
        float s = wp[(w0 + 0) * 2] + wp[(w0 + 1) * 2] + wp[(w0 + 2) * 2] + wp[(w0 + 3) * 2];
        float mx = fmaxf(fmaxf(wp[(w0 + 0) * 2 + 1], wp[(w0 + 1) * 2 + 1]),
                         fmaxf(wp[(w0 + 2) * 2 + 1], wp[(w0 + 3) * 2 + 1]));
        int b = m * 2 + tid;
        g_pool[(b * DM + d) * 2] = s;
        g_pool[(b * DM + d) * 2 + 1] = mx;
    }
}

// ---------------- head ----------------
__global__ void head_kernel(const float* __restrict__ W_head, const float* __restrict__ b_head,
                            float* __restrict__ out) {
    const int b = blockIdx.x;
    const int d = threadIdx.x;
    float avg = g_pool[(b * DM + d) * 2] * (1.0f / (float)T_TOTAL);
    float mx = g_pool[(b * DM + d) * 2 + 1];
    float contrib[NCLS];
    #pragma unroll
    for (int k = 0; k < NCLS; k++)
        contrib[k] = avg * W_head[d * NCLS + k] + mx * W_head[(DM + d) * NCLS + k];
    __shared__ float red[8][NCLS];
    int lane = d & 31, wid = d >> 5;
    #pragma unroll
    for (int k = 0; k < NCLS; k++) {
        float v = contrib[k];
        #pragma unroll
        for (int o = 16; o > 0; o >>= 1) v += __shfl_xor_sync(0xffffffffu, v, o);
        if (lane == 0) red[wid][k] = v;
    }
    __syncthreads();
    if (d == 0) {
        #pragma unroll
        for (int k = 0; k < NCLS; k++) {
            float t = b_head[k];
            #pragma unroll
            for (int wq = 0; wq < 8; wq++) t += red[wq][k];
            out[b * NCLS + k] = t;
        }
    }
}

extern "C" void kernel_launch(void* const* d_in, const int* in_sizes, int n_in,
                              void* d_out, int out_size) {
    const float* x      = (const float*)d_in[0];
    const float* w_in   = (const float*)d_in[1];
    const float* b_in   = (const float*)d_in[2];
    const float* A_diag = (const float*)d_in[3];
    const float* B_in   = (const float*)d_in[4];
    const float* C_out  = (const float*)d_in[5];
    const float* D_skip = (const float*)d_in[6];
    const float* W_head = (const float*)d_in[7];
    const float* b_head = (const float*)d_in[8];
    float* out = (float*)d_out;

    cudaFuncSetAttribute(ssm_mma, cudaFuncAttributeMaxDynamicSharedMemorySize, SMEM_BYTES);
    xsplit<<<128, 256>>>(x);
    precompute<<<DM, 256>>>(w_in, b_in, A_diag, B_in, C_out, D_skip);
    ssm_mma<<<dim3(MT, DM), 256, SMEM_BYTES>>>(w_in, b_in);
    head_kernel<<<BATCH, 256>>>(W_head, b_head, out);
}

// round 7
// speedup vs baseline: 3.4101x; 1.5880x over previous
#include <cuda_runtime.h>
#include <cuda_fp16.h>
#include <cstdint>

#define BATCH 32
#define T_TOTAL 4096
#define DM 256
#define SN 64
#define NCLS 5
#define L 64
#define MT 16

// ---- gmem precomputed operands (pre-swizzled fp16) ----
__device__ __half g_x[BATCH * T_TOTAL];
__device__ __half g_P[DM * 4096];
__device__ __half g_M[DM * 4096];
__device__ __half g_Q[DM * 4096];
__device__ float g_beta[DM * L], g_zeta[DM * SN], g_aL[DM * SN];
__device__ float g_pool[BATCH * DM * 2];

// ---- smem layout (bytes) ----
#define OFF_BETA 0
#define OFF_WP   256
#define OFF_X    512               /* 128 x 128B fp16 */
#define OFF_S    16896             /* 128 x 128B fp16 seeds */
#define OFF_U    33280             /* P then M: 64 x 128B */
#define OFF_Q    41472             /* 64 x 128B */
#define OFF_F    49664             /* fp16, 128 rows x 66 elems */
#define SMEM_BYTES 66560

__device__ __forceinline__ uint32_t smem_u32(const void* p) {
    uint32_t a;
    asm("{ .reg .u64 t; cvta.to.shared.u64 t, %1; cvt.u32.u64 %0, t; }" : "=r"(a) : "l"(p));
    return a;
}
#define CP16(dst, src) asm volatile("cp.async.cg.shared.global [%0], [%1], 16;" :: "r"(dst), "l"(src))
#define CP_COMMIT()    asm volatile("cp.async.commit_group;" ::: "memory")
#define CP_WAIT0()     asm volatile("cp.async.wait_group 0;" ::: "memory")

__device__ __forceinline__ void ldsm4(uint32_t addr, uint32_t r[4]) {
    asm volatile("ldmatrix.sync.aligned.m8n8.x4.shared.b16 {%0,%1,%2,%3}, [%4];"
                 : "=r"(r[0]), "=r"(r[1]), "=r"(r[2]), "=r"(r[3]) : "r"(addr));
}
__device__ __forceinline__ void mma_f16(float c[4], const uint32_t a[4], uint32_t b0, uint32_t b1) {
    asm volatile("mma.sync.aligned.m16n8k16.row.col.f32.f16.f16.f32 "
                 "{%0,%1,%2,%3}, {%4,%5,%6,%7}, {%8,%9}, {%0,%1,%2,%3};"
                 : "+f"(c[0]), "+f"(c[1]), "+f"(c[2]), "+f"(c[3])
                 : "r"(a[0]), "r"(a[1]), "r"(a[2]), "r"(a[3]), "r"(b0), "r"(b1));
}
// swizzled elem index within a 128B-row fp16 tile
__device__ __forceinline__ int swzi(int row, int col) {
    return ((row * 128 + col * 2) ^ ((row & 7) << 4)) >> 1;
}

// single-product fp16 matmul-accumulate: C[16 x 64] += A(16xK64) * B(64xK64)^T
__device__ __forceinline__ void mm1(float C[8][4], uint32_t aBase, uint32_t bBase,
                                    int lane, int row0) {
    const int arow = row0 + (lane & 15);
    const uint32_t abase = (uint32_t)arow * 128;
    const uint32_t axor = (uint32_t)(arow & 7) << 4;
    const uint32_t ak16 = ((lane >> 4) & 1) * 16;
    const int brow = ((lane >> 3) & 2) * 4 + (lane & 7);
    const uint32_t bxor = (uint32_t)(brow & 7) << 4;
    const uint32_t bk16 = ((lane >> 3) & 1) * 16;
    #pragma unroll
    for (int kc = 0; kc < 4; kc++) {
        uint32_t a[4];
        ldsm4(aBase + abase + ((ak16 + kc * 32) ^ axor), a);
        #pragma unroll
        for (int j = 0; j < 4; j++) {
            uint32_t boff = (uint32_t)(j * 16 + brow) * 128 + ((bk16 + kc * 32) ^ bxor);
            uint32_t b[4];
            ldsm4(bBase + boff, b);
            mma_f16(C[2 * j],     a, b[0], b[1]);
            mma_f16(C[2 * j + 1], a, b[2], b[3]);
        }
    }
}

// ---------------- x -> fp16, pre-swizzled ----------------
__global__ void xsplit(const float* __restrict__ x) {
    int e = (blockIdx.x * 256 + threadIdx.x) * 4;
    float4 v = *reinterpret_cast<const float4*>(x + e);
    int b = e >> 12, t = e & 4095;
    int rg = b * 64 + (t >> 6), col = t & 63;
    int boff = rg * 128 + ((col * 2) ^ ((rg & 7) << 4));
    __half2 p0 = __floats2half2_rn(v.x, v.y);
    __half2 p1 = __floats2half2_rn(v.z, v.w);
    char* p = (char*)g_x + boff;
    *(__half2*)p = p0;
    *(__half2*)(p + 4) = p1;
}

// ---------------- per-d operator tiles ----------------
__global__ void precompute(const float* __restrict__ w_in, const float* __restrict__ b_in,
                           const float* __restrict__ A_diag, const float* __restrict__ B_in,
                           const float* __restrict__ C_out, const float* __restrict__ D_skip) {
    const int d = blockIdx.x;
    const int tid = threadIdx.x;
    const int n = tid & 63, q = tid >> 6;
    __shared__ float gmat[64][65];
    __shared__ float Kp[64][4];
    __shared__ float Ksm[64];
    __shared__ float zp[4][64];

    float a = A_diag[d * 64 + n];
    float g = B_in[d * 64 + n] * C_out[d * 64 + n];
    float a2 = a * a, a4 = a2 * a2, a8 = a4 * a4, a16 = a8 * a8;
    float a32 = a16 * a16, a48 = a32 * a16, a64v = a32 * a32;
    float s = (q == 0) ? 1.f : ((q == 1) ? a16 : ((q == 2) ? a32 : a48));

    {   // P[n][tau] = a^(63-tau); zeta partial
        float p = s, zs = 0.f;
        #pragma unroll
        for (int j = 0; j < 16; j++) {
            int e = q * 16 + j, tau = 63 - e;
            g_P[d * 4096 + swzi(n, tau)] = __float2half_rn(p);
            zs += p; p *= a;
        }
        zp[q][n] = zs;
    }
    {   // Q[i][n] = g*a^(i+1)
        float t = g * s * a;
        #pragma unroll
        for (int j = 0; j < 16; j++) {
            int i = q * 16 + j;
            g_Q[d * 4096 + swzi(i, n)] = __float2half_rn(t);
            t *= a;
        }
    }
    {   // gmat[delta][n] = g*a^delta
        float u = g * s;
        #pragma unroll
        for (int j = 0; j < 16; j++) { gmat[q * 16 + j][n] = u; u *= a; }
    }
    __syncthreads();
    if (q == 0) {
        g_zeta[d * 64 + n] = zp[0][n] + zp[1][n] + zp[2][n] + zp[3][n];
        g_aL[d * 64 + n] = a64v;
    }
    {   // K[delta] partial over n
        float ss = 0.f;
        #pragma unroll
        for (int j = 0; j < 16; j++) ss += gmat[n][q * 16 + j];
        Kp[n][q] = ss;
    }
    __syncthreads();
    if (tid < 64) Ksm[tid] = Kp[tid][0] + Kp[tid][1] + Kp[tid][2] + Kp[tid][3];
    __syncthreads();
    float w = w_in[d], bb = b_in[d], dsk = D_skip[d];
    if (tid < 64) {
        float kap = 0.f;
        for (int dd = 0; dd <= tid; dd++) kap += Ksm[dd];
        g_beta[d * 64 + tid] = bb * kap + dsk * bb;
    }
    {   // M[i][tau] = w*K[i-tau] (tau<=i), + dsk*w on diag
        int i = n;
        #pragma unroll
        for (int j = 0; j < 16; j++) {
            int tau = q * 16 + j;
            float val = (tau <= i) ? w * Ksm[i - tau] : 0.f;
            if (tau == i) val += dsk * w;
            g_M[d * 4096 + swzi(i, tau)] = __float2half_rn(val);
        }
    }
}

// ---------------- fused SSM: one CTA per (row-tile m, channel d) ----------------
__global__ __launch_bounds__(256, 3)
void ssm_mma(const float* __restrict__ w_in, const float* __restrict__ b_in) {
    extern __shared__ char smem[];
    const uint32_t sb = smem_u32(smem);
    const int tid = threadIdx.x, wid = tid >> 5, lane = tid & 31;
    const int m = blockIdx.x, d = blockIdx.y;

    if (tid < 64) reinterpret_cast<float*>(smem + OFF_BETA)[tid] = g_beta[d * 64 + tid];

    {   // cp.async staging: X, P, Q
        const char* xp = (const char*)g_x + (size_t)m * 16384;
        #pragma unroll
        for (int k = 0; k < 4; k++) {
            int i = (tid + k * 256) * 16;
            CP16(sb + OFF_X + i, xp + i);
        }
        const char* pp = (const char*)g_P + d * 8192;
        const char* qp = (const char*)g_Q + d * 8192;
        #pragma unroll
        for (int k = 0; k < 2; k++) {
            int i = (tid + k * 256) * 16;
            CP16(sb + OFF_U + i, pp + i);
            CP16(sb + OFF_Q + i, qp + i);
        }
    }
    CP_COMMIT(); CP_WAIT0();
    __syncthreads();

    // MMA1: F = X . P^T
    float C1[8][4];
    #pragma unroll
    for (int i = 0; i < 8; i++)
        #pragma unroll
        for (int k = 0; k < 4; k++) C1[i][k] = 0.f;
    mm1(C1, sb + OFF_X, sb + OFF_U, lane, wid * 16);

    {   // store F as fp16 (pitch 66)
        __half* F = reinterpret_cast<__half*>(smem + OFF_F);
        int rg = wid * 16 + (lane >> 2), cb = (lane & 3) * 2;
        #pragma unroll
        for (int nt = 0; nt < 8; nt++) {
            *reinterpret_cast<__half2*>(F + rg * 66 + nt * 8 + cb) =
                __floats2half2_rn(C1[nt][0], C1[nt][1]);
            *reinterpret_cast<__half2*>(F + (rg + 8) * 66 + nt * 8 + cb) =
                __floats2half2_rn(C1[nt][2], C1[nt][3]);
        }
    }
    __syncthreads();

    // warps 0-3: inter-chunk scan -> fp16 seeds | warps 4-7: copy M over dead P
    if (wid < 4) {
        int bl = tid >> 6, n = tid & 63;
        float aLv = g_aL[d * 64 + n];
        float w = w_in[d];
        float bz = b_in[d] * g_zeta[d * 64 + n];
        const __half* F = reinterpret_cast<const __half*>(smem + OFF_F);
        float r = 0.f;
        #pragma unroll 8
        for (int c = 0; c < 64; c++) {
            int row = bl * 64 + c;
            *reinterpret_cast<__half*>(smem + OFF_S + row * 128 + ((n * 2) ^ ((c & 7) << 4))) =
                __float2half_rn(r);
            r = fmaf(aLv, r, fmaf(w, __half2float(F[row * 66 + n]), bz));
        }
    } else {
        const char* mp = (const char*)g_M + d * 8192;
        int t2 = tid - 128;
        #pragma unroll
        for (int k = 0; k < 4; k++) {
            int i = (t2 + k * 128) * 16;
            CP16(sb + OFF_U + i, mp + i);
        }
        CP_COMMIT(); CP_WAIT0();
    }
    __syncthreads();

    // MMA2: y = X.M'^T + S.Q^T ; epilogue gelu+pool
    float C2[8][4];
    #pragma unroll
    for (int i = 0; i < 8; i++)
        #pragma unroll
        for (int k = 0; k < 4; k++) C2[i][k] = 0.f;
    mm1(C2, sb + OFF_X, sb + OFF_U, lane, wid * 16);
    mm1(C2, sb + OFF_S, sb + OFF_Q, lane, wid * 16);

    {
        const float* beta = reinterpret_cast<const float*>(smem + OFF_BETA);
        float ps = 0.f, pm = -3.402823466e38f;
        #pragma unroll
        for (int nt = 0; nt < 8; nt++) {
            float2 b2 = *reinterpret_cast<const float2*>(beta + nt * 8 + (lane & 3) * 2);
            #pragma unroll
            for (int k = 0; k < 4; k++) {
                float ypre = C2[nt][k] + ((k & 1) ? b2.y : b2.x);
                float inner = 0.7978845608028654f * ypre * fmaf(0.044715f, ypre * ypre, 1.0f);
                float th; asm("tanh.approx.f32 %0, %1;" : "=f"(th) : "f"(inner));
                float h = 0.5f * ypre * (1.0f + th);
                ps += h;
                pm = fmaxf(pm, h);
            }
        }
        #pragma unroll
        for (int o = 16; o > 0; o >>= 1) {
            ps += __shfl_xor_sync(0xffffffffu, ps, o);
            pm = fmaxf(pm, __shfl_xor_sync(0xffffffffu, pm, o));
        }
        float* wp = reinterpret_cast<float*>(smem + OFF_WP);
        if (lane == 0) { wp[wid * 2] = ps; wp[wid * 2 + 1] = pm; }
    }
    __syncthreads();
    if (tid < 2) {
        const float* wp = reinterpret_cast<const float*>(smem + OFF_WP);
        int w0 = tid * 4;
        float s = wp[(w0 + 0) * 2] + wp[(w0 + 1) * 2] + wp[(w0 + 2) * 2] + wp[(w0 + 3) * 2];
        float mx = fmaxf(fmaxf(wp[(w0 + 0) * 2 + 1], wp[(w0 + 1) * 2 + 1]),
                         fmaxf(wp[(w0 + 2) * 2 + 1], wp[(w0 + 3) * 2 + 1]));
        int b = m * 2 + tid;
        g_pool[(b * DM + d) * 2] = s;
        g_pool[(b * DM + d) * 2 + 1] = mx;
    }
}

// ---------------- head ----------------
__global__ void head_kernel(const float* __restrict__ W_head, const float* __restrict__ b_head,
                            float* __restrict__ out) {
    const int b = blockIdx.x;
    const int d = threadIdx.x;
    float avg = g_pool[(b * DM + d) * 2] * (1.0f / (float)T_TOTAL);
    float mx = g_pool[(b * DM + d) * 2 + 1];
    float contrib[NCLS];
    #pragma unroll
    for (int k = 0; k < NCLS; k++)
        contrib[k] = avg * W_head[d * NCLS + k] + mx * W_head[(DM + d) * NCLS + k];
    __shared__ float red[8][NCLS];
    int lane = d & 31, wid = d >> 5;
    #pragma unroll
    for (int k = 0; k < NCLS; k++) {
        float v = contrib[k];
        #pragma unroll
        for (int o = 16; o > 0; o >>= 1) v += __shfl_xor_sync(0xffffffffu, v, o);
        if (lane == 0) red[wid][k] = v;
    }
    __syncthreads();
    if (d == 0) {
        #pragma unroll
        for (int k = 0; k < NCLS; k++) {
            float t = b_head[k];
            #pragma unroll
            for (int wq = 0; wq < 8; wq++) t += red[wq][k];
            out[b * NCLS + k] = t;
        }
    }
}

extern "C" void kernel_launch(void* const* d_in, const int* in_sizes, int n_in,
                              void* d_out, int out_size) {
    const float* x      = (const float*)d_in[0];
    const float* w_in   = (const float*)d_in[1];
    const float* b_in   = (const float*)d_in[2];
    const float* A_diag = (const float*)d_in[3];
    const float* B_in   = (const float*)d_in[4];
    const float* C_out  = (const float*)d_in[5];
    const float* D_skip = (const float*)d_in[6];
    const float* W_head = (const float*)d_in[7];
    const float* b_head = (const float*)d_in[8];
    float* out = (float*)d_out;

    cudaFuncSetAttribute(ssm_mma, cudaFuncAttributeMaxDynamicSharedMemorySize, SMEM_BYTES);
    xsplit<<<128, 256>>>(x);
    precompute<<<DM, 256>>>(w_in, b_in, A_diag, B_in, C_out, D_skip);
    ssm_mma<<<dim3(MT, DM), 256, SMEM_BYTES>>>(w_in, b_in);
    head_kernel<<<BATCH, 256>>>(W_head, b_head, out);
}